// round 5
// baseline (speedup 1.0000x reference)
#include <cuda_runtime.h>

// ---------------- problem constants ----------------
#define T_STEPS 131   // 128 story + 1 query + 2 empty
#define BSZ     64
#define EMB     128
#define HID     256
#define VOCAB   32000
#define MSTL    128
#define MSEL    24
#define QL      16

// ---------------- scratch ----------------
// d_X: [t(<=128)][bt16][e128][b4]  (per-CTA tile contiguous 2KB)
__device__ __align__(16) float d_X[129 * 16 * EMB * 4];
// d_H: final hidden state only: [bt16][k256][b4]
__device__ __align__(16) float d_H[16 * HID * 4];

// ---------------- helpers ----------------
typedef unsigned long long u64;

__device__ __forceinline__ u64 pack2(float x, float y) {
    u64 r; asm("mov.b64 %0, {%1, %2};" : "=l"(r) : "f"(x), "f"(y)); return r;
}
__device__ __forceinline__ void ffma2(u64& acc, u64 a, u64 b) {
    asm("fma.rn.f32x2 %0, %1, %2, %0;" : "+l"(acc) : "l"(a), "l"(b));
}
__device__ __forceinline__ void lds_2x64(u64& p0, u64& p1, unsigned addr) {
    asm volatile("ld.shared.v2.u64 {%0, %1}, [%2];" : "=l"(p0), "=l"(p1) : "r"(addr));
}
__device__ __forceinline__ void sts_2x64(unsigned addr, u64 p0, u64 p1) {
    asm volatile("st.shared.v2.u64 [%0], {%1, %2};" :: "r"(addr), "l"(p0), "l"(p1));
}
__device__ __forceinline__ void unpack2(u64 p, float& x, float& y) {
    asm("mov.b64 {%0, %1}, %2;" : "=f"(x), "=f"(y) : "l"(p));
}
__device__ __forceinline__ float lds_f32(unsigned addr) {
    float v; asm volatile("ld.shared.f32 %0, [%1];" : "=f"(v) : "r"(addr)); return v;
}
__device__ __forceinline__ void cp_async16(unsigned smem, const void* gptr) {
    asm volatile("cp.async.cg.shared.global [%0], [%1], 16;" :: "r"(smem), "l"(gptr));
}
__device__ __forceinline__ void cp_commit() { asm volatile("cp.async.commit_group;"); }
__device__ __forceinline__ void cp_wait0()  { asm volatile("cp.async.wait_group 0;"); }

__device__ __forceinline__ unsigned mapa_rank(unsigned addr, unsigned rank) {
    unsigned r;
    asm("mapa.shared::cluster.u32 %0, %1, %2;" : "=r"(r) : "r"(addr), "r"(rank));
    return r;
}
__device__ __forceinline__ void st_cluster_f32(unsigned addr, float v) {
    asm volatile("st.shared::cluster.f32 [%0], %1;" :: "r"(addr), "f"(v));
}
__device__ __forceinline__ unsigned ctarank() {
    unsigned r; asm("mov.u32 %0, %%cluster_ctarank;" : "=r"(r)); return r;
}
#define CLUSTER_ARRIVE() asm volatile("barrier.cluster.arrive.aligned;" ::: "memory")
#define CLUSTER_WAIT()   asm volatile("barrier.cluster.wait.aligned;"   ::: "memory")

__device__ __forceinline__ float sigf(float x) {
    return 1.0f / (1.0f + __expf(-x));
}
__device__ __forceinline__ float tanh_f(float x) {
    float a = fabsf(x);
    float e = __expf(-2.0f * a);
    float r = (1.0f - e) / (1.0f + e);
    return copysignf(r, x);
}

// ============================================================================
// Kernel 1: embedding gather + position encoding -> d_X [t][bt16][e][4b]
// ============================================================================
__global__ void encode_kernel(const int* __restrict__ story,
                              const int* __restrict__ query,
                              const float* __restrict__ E) {
    int wid  = blockIdx.x * 8 + (threadIdx.x >> 5);
    int lane = threadIdx.x & 31;
    int b = wid / T_STEPS;
    int t = wid % T_STEPS;
    if (t > MSTL) return;
    int e0 = lane * 4;

    const float invE = 1.0f / (float)EMB;
    float k0 = (e0 + 1) * invE;
    float k1 = (e0 + 2) * invE;
    float k2 = (e0 + 3) * invE;
    float k3 = (e0 + 4) * invE;

    float4 acc = make_float4(0.f, 0.f, 0.f, 0.f);

    if (t < MSTL) {
        const int* toks = story + (b * MSTL + t) * MSEL;
#pragma unroll
        for (int s = 0; s < MSEL; ++s) {
            int tok = toks[s];
            float j = (s + 1) * (1.0f / 32.0f);
            float A = 1.0f - j, Bc = 1.0f - 2.0f * j;
            float4 ev = *(const float4*)(E + tok * EMB + e0);
            acc.x += ev.x * (A - k0 * Bc);
            acc.y += ev.y * (A - k1 * Bc);
            acc.z += ev.z * (A - k2 * Bc);
            acc.w += ev.w * (A - k3 * Bc);
        }
    } else {
        const int* toks = query + b * QL;
#pragma unroll
        for (int s = 0; s < QL; ++s) {
            int tok = toks[s];
            float j = (s + 1) * (1.0f / 32.0f);
            float A = 1.0f - j, Bc = 1.0f - 2.0f * j;
            float4 ev = *(const float4*)(E + tok * EMB + e0);
            acc.x += ev.x * (A - k0 * Bc);
            acc.y += ev.y * (A - k1 * Bc);
            acc.z += ev.z * (A - k2 * Bc);
            acc.w += ev.w * (A - k3 * Bc);
        }
    }
    float* dst = d_X + ((t * 16 + (b >> 2)) * EMB) * 4 + (b & 3);
    dst[(e0 + 0) * 4] = acc.x;
    dst[(e0 + 1) * 4] = acc.y;
    dst[(e0 + 2) * 4] = acc.z;
    dst[(e0 + 3) * 4] = acc.w;
}

// ============================================================================
// Kernel 2: persistent LSTM recurrence, DSMEM h-exchange via cluster(8)
//   grid 128 CTAs = 16 bt-groups x 8 ht (cluster rank). 512 threads:
//   kc = tid>>7 (k-chunk 0..3), r = tid&127 (gate row g*32+jj within tile).
// ============================================================================
#define RGRID 128
#define RTHREADS 512

// shared layout (float offsets)
#define OFF_WIH 0                       // [k128][r128]      64KB
#define OFF_HSH (128 * 128)             // 2 x [k256][b4]     8KB
#define OFF_XSH (OFF_HSH + 2048)        // 2 x [e128][b4]     4KB
#define OFF_PSH (OFF_XSH + 1024)        // [kc*128+r][b4]     8KB
#define OFF_BSH (OFF_PSH + 2048)        // 128
#define LSTM_SMEM_FLOATS (OFF_BSH + 128)
#define LSTM_SMEM_BYTES  (LSTM_SMEM_FLOATS * 4)
#define HSH_BUF_BYTES 4096

__global__ void __launch_bounds__(RTHREADS, 1) __cluster_dims__(8, 1, 1)
lstm_kernel(const float* __restrict__ W_ih, const float* __restrict__ W_hh,
            const float* __restrict__ b_ih, const float* __restrict__ b_hh) {
    extern __shared__ float sm[];
    const unsigned smb = (unsigned)__cvta_generic_to_shared(sm);

    const int tid = threadIdx.x;
    const int ht  = (int)ctarank();        // 0..7 (32 hidden units each)
    const int bt  = blockIdx.x >> 3;       // 0..15 (4 batches each)
    const int kc  = tid >> 7;              // 0..3
    const int r   = tid & 127;             // g*32 + jj
    const int grow = (r >> 5) * 256 + ht * 32 + (r & 31);

    // ---- stage W_ih transposed [k][r] into SMEM (one-time) ----
    for (int idx = tid; idx < 128 * 128; idx += RTHREADS) {
        int rr = idx >> 7, k = idx & 127;
        int gr = (rr >> 5) * 256 + ht * 32 + (rr & 31);
        sm[OFF_WIH + k * 128 + rr] = W_ih[gr * EMB + k];
    }
    // ---- W_hh slice register-resident: row grow, k in [kc*64, kc*64+64) ----
    float4 whh[16];
    {
        const float4* ph = (const float4*)(W_hh + grow * HID + kc * 64);
#pragma unroll
        for (int q = 0; q < 16; ++q) whh[q] = ph[q];
    }
    if (tid < 128) {
        int gr = (tid >> 5) * 256 + ht * 32 + (tid & 31);
        sm[OFF_BSH + tid] = b_ih[gr] + b_hh[gr];
    }

    // ---- precompute DSMEM addresses for this thread's h value ----
    const int jj = (tid >> 2) & 31;        // meaningful for tid<128
    const int bb = tid & 3;
    unsigned raddr[8];
    {
        unsigned local = smb + (OFF_HSH + ((ht * 32 + jj) * 4 + bb)) * 4;
#pragma unroll
        for (int rk = 0; rk < 8; ++rk) raddr[rk] = mapa_rank(local, (unsigned)rk);
    }

    const unsigned xs0 = smb + OFF_XSH * 4;
    const unsigned wib = smb + OFF_WIH * 4 + (kc * 32) * 128 * 4 + r * 4;
    const unsigned pbase = smb + OFF_PSH * 4 + tid * 16;

    // prefetch x(0)
    if (tid < 128)
        cp_async16(xs0 + tid * 16, d_X + (bt * EMB) * 4 + tid * 4);
    cp_commit();

    float c = 0.0f;
    __syncthreads();   // Wih_s / bsh ready

    for (int t = 0; t < T_STEPS; ++t) {
        u64 a0 = 0, a1 = 0;

        if (t <= MSTL) {
            cp_wait0();
            __syncthreads();                       // x(t) visible; prev reads done
            if (t < MSTL) {
                if (tid < 128)
                    cp_async16(xs0 + (((t + 1) & 1) ? 2048 : 0) + tid * 16,
                               d_X + (((t + 1) * 16 + bt) * EMB) * 4 + tid * 4);
                cp_commit();
            }
            // ---- x-part GEMM (off critical path; overlaps cluster skew) ----
            const unsigned xb = xs0 + ((t & 1) ? 2048 : 0) + (kc * 32) * 16;
#pragma unroll
            for (int k = 0; k < 32; ++k) {
                float w = lds_f32(wib + k * 512);
                u64 wd = pack2(w, w);
                u64 p0, p1;
                lds_2x64(p0, p1, xb + k * 16);
                ffma2(a0, wd, p0);
                ffma2(a1, wd, p1);
            }
        }

        if (t > 0) {
            CLUSTER_WAIT();    // acquire: h(t-1) present in hsh buf (t&1)^1
            const unsigned hb = smb + OFF_HSH * 4 + ((t & 1) ^ 1) * HSH_BUF_BYTES
                                + (kc * 64) * 16;
#pragma unroll
            for (int q = 0; q < 16; ++q) {
                float4 w4 = whh[q];
#pragma unroll
                for (int cc = 0; cc < 4; ++cc) {
                    float w = (cc == 0) ? w4.x : (cc == 1) ? w4.y : (cc == 2) ? w4.z : w4.w;
                    u64 wd = pack2(w, w);
                    u64 p0, p1;
                    lds_2x64(p0, p1, hb + (q * 4 + cc) * 16);
                    ffma2(a0, wd, p0);
                    ffma2(a1, wd, p1);
                }
            }
        }

        sts_2x64(pbase, a0, a1);
        __syncthreads();

        // ---- reduce + gates + state update + DSMEM broadcast ----
        if (tid < 128) {
            const unsigned pb = smb + OFF_PSH * 4;
            float v[4];
#pragma unroll
            for (int g = 0; g < 4; ++g) {
                int rr = g * 32 + jj;
                float s = sm[OFF_BSH + rr];
#pragma unroll
                for (int k4 = 0; k4 < 4; ++k4)
                    s += lds_f32(pb + ((k4 * 128 + rr) * 4 + bb) * 4);
                v[g] = s;
            }
            float ig = sigf(v[0]);
            float fg = sigf(v[1]);
            float gv = tanh_f(v[2]);
            float og = sigf(v[3]);
            c = fg * c + ig * gv;
            float h = og * tanh_f(c);
            if (t < T_STEPS - 1) {
                // broadcast h into all 8 peers' hsh buf (t&1)
                unsigned boff = (t & 1) * HSH_BUF_BYTES;
#pragma unroll
                for (int rk = 0; rk < 8; ++rk) st_cluster_f32(raddr[rk] + boff, h);
            } else {
                // last step: nobody reads hsh again — only the global result.
                // (Remote stores here would race with peer CTA exit.)
                d_H[bt * (HID * 4) + (ht * 32 + jj) * 4 + bb] = h;
            }
        }
        __syncthreads();                 // psh reads done; remote sts issued

        if (t < T_STEPS - 1) CLUSTER_ARRIVE();   // release: publish h(t)
    }

    // no CTA may exit while peers could still have cluster-window traffic
    CLUSTER_ARRIVE();
    CLUSTER_WAIT();
}

// ============================================================================
// Kernel 3: logits = h @ lin_W.T + lin_b  ([64,256] x [256,32000]), f32x2
// ============================================================================
__global__ void __launch_bounds__(256, 1)
out_kernel(const float* __restrict__ lin_W, const float* __restrict__ lin_b,
           float* __restrict__ out) {
    extern __shared__ float hsh[];  // [256 k][64 b], 64 KB
    const int tid = threadIdx.x;
    {
        // d_H [bt16][k256][4b] -> hsh [k][64b]
        const float4* src = (const float4*)d_H;   // one float4 = (k, 4 batches)
        for (int idx4 = tid; idx4 < 4096; idx4 += 256) {
            int btx = idx4 >> 8, k = idx4 & 255;
            *(float4*)(hsh + k * 64 + btx * 4) = src[idx4];
        }
    }
    __syncthreads();

    const int v = blockIdx.x * 256 + tid;
    const unsigned hb = (unsigned)__cvta_generic_to_shared(hsh);

    float bbv = lin_b[v];
    u64 acc[32];
    u64 bp = pack2(bbv, bbv);
#pragma unroll
    for (int j = 0; j < 32; ++j) acc[j] = bp;

    const float4* wp = (const float4*)(lin_W + v * HID);
#pragma unroll 4
    for (int kk = 0; kk < HID / 4; ++kk) {
        float4 w4 = wp[kk];
#pragma unroll
        for (int cc = 0; cc < 4; ++cc) {
            float w = (cc == 0) ? w4.x : (cc == 1) ? w4.y : (cc == 2) ? w4.z : w4.w;
            u64 wd = pack2(w, w);
            unsigned base = hb + ((kk * 4 + cc) * BSZ) * 4;
#pragma unroll
            for (int p = 0; p < 8; ++p) {
                u64 q0, q1, q2, q3;
                lds_2x64(q0, q1, base + p * 32);
                lds_2x64(q2, q3, base + p * 32 + 16);
                ffma2(acc[p * 4 + 0], wd, q0);
                ffma2(acc[p * 4 + 1], wd, q1);
                ffma2(acc[p * 4 + 2], wd, q2);
                ffma2(acc[p * 4 + 3], wd, q3);
            }
        }
    }
#pragma unroll
    for (int j = 0; j < 32; ++j) {
        float f0, f1;
        unpack2(acc[j], f0, f1);
        out[(2 * j) * VOCAB + v]     = f0;
        out[(2 * j + 1) * VOCAB + v] = f1;
    }
}

// ============================================================================
// launch
// ============================================================================
extern "C" void kernel_launch(void* const* d_in, const int* in_sizes, int n_in,
                              void* d_out, int out_size) {
    const int*   story  = (const int*)d_in[0];
    const int*   query  = (const int*)d_in[1];
    const float* E      = (const float*)d_in[2];
    const float* W_ih   = (const float*)d_in[3];
    const float* W_hh   = (const float*)d_in[4];
    const float* b_ih   = (const float*)d_in[5];
    const float* b_hh   = (const float*)d_in[6];
    const float* lin_W  = (const float*)d_in[7];
    const float* lin_b  = (const float*)d_in[8];
    float*       out    = (float*)d_out;

    cudaFuncSetAttribute(lstm_kernel, cudaFuncAttributeMaxDynamicSharedMemorySize,
                         LSTM_SMEM_BYTES);
    cudaFuncSetAttribute(out_kernel, cudaFuncAttributeMaxDynamicSharedMemorySize,
                         HID * BSZ * 4);

    encode_kernel<<<(T_STEPS * BSZ) / 8, 256>>>(story, query, E);
    lstm_kernel<<<RGRID, RTHREADS, LSTM_SMEM_BYTES>>>(W_ih, W_hh, b_ih, b_hh);
    out_kernel<<<VOCAB / 256, 256, HID * BSZ * 4>>>(lin_W, lin_b, out);
}

// round 6
// speedup vs baseline: 1.5668x; 1.5668x over previous
#include <cuda_runtime.h>

// ---------------- problem constants ----------------
#define T_STEPS 131   // 128 story + 1 query + 2 empty
#define BSZ     64
#define EMB     128
#define HID     256
#define VOCAB   32000
#define MSTL    128
#define MSEL    24
#define QL      16

// ---------------- scratch ----------------
// d_X: [t(<=128)][bt8][e128][b8]  (per-CTA tile contiguous 4KB)
__device__ __align__(16) float d_X[129 * 8 * EMB * 8];
// d_H: h double buffer [buf2][bt8][k256][b8] (per-CTA block = 512B contiguous)
__device__ __align__(16) float d_H[2 * 8 * HID * 8];
// one flag per (t, bt, producer ht); cleared before each run
#define NFLAGS (T_STEPS * 8 * 16)
__device__ unsigned d_flag[NFLAGS];

// ---------------- helpers ----------------
typedef unsigned long long u64;

__device__ __forceinline__ u64 pack2(float x, float y) {
    u64 r; asm("mov.b64 %0, {%1, %2};" : "=l"(r) : "f"(x), "f"(y)); return r;
}
__device__ __forceinline__ void ffma2(u64& acc, u64 a, u64 b) {
    asm("fma.rn.f32x2 %0, %1, %2, %0;" : "+l"(acc) : "l"(a), "l"(b));
}
__device__ __forceinline__ void lds_2x64(u64& p0, u64& p1, unsigned addr) {
    asm volatile("ld.shared.v2.u64 {%0, %1}, [%2];" : "=l"(p0), "=l"(p1) : "r"(addr));
}
__device__ __forceinline__ void sts_2x64(unsigned addr, u64 p0, u64 p1) {
    asm volatile("st.shared.v2.u64 [%0], {%1, %2};" :: "r"(addr), "l"(p0), "l"(p1));
}
__device__ __forceinline__ void unpack2(u64 p, float& x, float& y) {
    asm("mov.b64 {%0, %1}, %2;" : "=f"(x), "=f"(y) : "l"(p));
}
__device__ __forceinline__ float lds_f32(unsigned addr) {
    float v; asm volatile("ld.shared.f32 %0, [%1];" : "=f"(v) : "r"(addr)); return v;
}
__device__ __forceinline__ void cp_async16(unsigned smem, const void* gptr) {
    asm volatile("cp.async.cg.shared.global [%0], [%1], 16;" :: "r"(smem), "l"(gptr));
}
__device__ __forceinline__ void cp_commit() { asm volatile("cp.async.commit_group;"); }
__device__ __forceinline__ void cp_wait0()  { asm volatile("cp.async.wait_group 0;"); }

__device__ __forceinline__ unsigned ld_acq(const unsigned* p) {
    unsigned v;
    asm volatile("ld.acquire.gpu.global.b32 %0, [%1];" : "=r"(v) : "l"(p));
    return v;
}
__device__ __forceinline__ void st_rel(unsigned* p, unsigned v) {
    asm volatile("st.release.gpu.global.b32 [%0], %1;" :: "l"(p), "r"(v));
}

__device__ __forceinline__ float sigf(float x) {
    return 1.0f / (1.0f + __expf(-x));
}
__device__ __forceinline__ float tanh_f(float x) {
    float a = fabsf(x);
    float e = __expf(-2.0f * a);
    float r = (1.0f - e) / (1.0f + e);
    return copysignf(r, x);
}

// ============================================================================
// Kernel 0: clear flags (graph replays must start from zero)
// ============================================================================
__global__ void clear_flags_kernel() {
    int i = blockIdx.x * 256 + threadIdx.x;
    if (i < NFLAGS) d_flag[i] = 0;
}

// ============================================================================
// Kernel 1: embedding gather + position encoding -> d_X [t][bt8][e][8b]
// ============================================================================
__global__ void encode_kernel(const int* __restrict__ story,
                              const int* __restrict__ query,
                              const float* __restrict__ E) {
    int wid  = blockIdx.x * 8 + (threadIdx.x >> 5);
    int lane = threadIdx.x & 31;
    int b = wid / T_STEPS;
    int t = wid % T_STEPS;
    if (t > MSTL) return;
    int e0 = lane * 4;

    const float invE = 1.0f / (float)EMB;
    float k0 = (e0 + 1) * invE;
    float k1 = (e0 + 2) * invE;
    float k2 = (e0 + 3) * invE;
    float k3 = (e0 + 4) * invE;

    float4 acc = make_float4(0.f, 0.f, 0.f, 0.f);

    if (t < MSTL) {
        const int* toks = story + (b * MSTL + t) * MSEL;
#pragma unroll
        for (int s = 0; s < MSEL; ++s) {
            int tok = toks[s];
            float j = (s + 1) * (1.0f / 32.0f);
            float A = 1.0f - j, Bc = 1.0f - 2.0f * j;
            float4 ev = *(const float4*)(E + tok * EMB + e0);
            acc.x += ev.x * (A - k0 * Bc);
            acc.y += ev.y * (A - k1 * Bc);
            acc.z += ev.z * (A - k2 * Bc);
            acc.w += ev.w * (A - k3 * Bc);
        }
    } else {
        const int* toks = query + b * QL;
#pragma unroll
        for (int s = 0; s < QL; ++s) {
            int tok = toks[s];
            float j = (s + 1) * (1.0f / 32.0f);
            float A = 1.0f - j, Bc = 1.0f - 2.0f * j;
            float4 ev = *(const float4*)(E + tok * EMB + e0);
            acc.x += ev.x * (A - k0 * Bc);
            acc.y += ev.y * (A - k1 * Bc);
            acc.z += ev.z * (A - k2 * Bc);
            acc.w += ev.w * (A - k3 * Bc);
        }
    }
    float* dst = d_X + ((t * 8 + (b >> 3)) * EMB) * 8 + (b & 7);
    dst[(e0 + 0) * 8] = acc.x;
    dst[(e0 + 1) * 8] = acc.y;
    dst[(e0 + 2) * 8] = acc.z;
    dst[(e0 + 3) * 8] = acc.w;
}

// ============================================================================
// Kernel 2: persistent LSTM recurrence, flag-based L2 exchange
//   128 CTAs = 16 ht x 8 bt, 512 threads: kc=tid>>6 (k-chunk 0..7), r=tid&63.
// ============================================================================
#define RGRID 128
#define RTHREADS 512

__global__ void __launch_bounds__(RTHREADS, 1)
lstm_kernel(const float* __restrict__ W_ih, const float* __restrict__ W_hh,
            const float* __restrict__ b_ih, const float* __restrict__ b_hh) {
    __shared__ __align__(16) float xsh[2][EMB * 8];   // 2 x 4KB, [e][8b]
    __shared__ __align__(16) float hsh[HID * 8];      // 8KB, [k][8b]
    __shared__ __align__(16) float psh[512 * 8];      // 16KB partials
    __shared__ float bsh[64];

    const int tid = threadIdx.x;
    const int bt  = blockIdx.x & 7;
    const int ht  = blockIdx.x >> 3;
    const int kc  = tid >> 6;          // 0..7
    const int r   = tid & 63;          // g*16 + jj
    const int grow = (r >> 4) * 256 + ht * 16 + (r & 15);

    // ---- register-resident weight slices ----
    float4 wih[4];    // W_ih[grow][kc*16 .. +16)
    float4 whh[8];    // W_hh[grow][kc*32 .. +32)
    {
        const float4* p = (const float4*)(W_ih + grow * EMB + kc * 16);
#pragma unroll
        for (int q = 0; q < 4; ++q) wih[q] = p[q];
        const float4* ph = (const float4*)(W_hh + grow * HID + kc * 32);
#pragma unroll
        for (int q = 0; q < 8; ++q) whh[q] = ph[q];
    }
    if (tid < 64) {
        int gr = (tid >> 4) * 256 + ht * 16 + (tid & 15);
        bsh[tid] = b_ih[gr] + b_hh[gr];
    }

    const unsigned xs0  = (unsigned)__cvta_generic_to_shared(&xsh[0][0]);
    const unsigned hsb  = (unsigned)__cvta_generic_to_shared(hsh);
    const unsigned hbase = hsb + kc * 1024;                       // kc*32 rows * 32B
    const unsigned pbase = (unsigned)__cvta_generic_to_shared(psh) + tid * 32;

    const int w    = tid >> 5;   // warp id 0..15 (one producer each)
    const int lane = tid & 31;

    // prefetch x(0)
    if (tid < 256) cp_async16(xs0 + tid * 16, d_X + bt * (EMB * 8) + tid * 4);
    cp_commit();

    float c = 0.0f;
    __syncthreads();   // bsh ready

    for (int t = 0; t < T_STEPS; ++t) {
        u64 a0 = 0, a1 = 0, a2 = 0, a3 = 0;

        if (t <= MSTL) {
            cp_wait0();
            __syncthreads();                        // x(t) visible CTA-wide
            if (t < MSTL) {
                if (tid < 256)
                    cp_async16(xs0 + (((t + 1) & 1) ? 4096 : 0) + tid * 16,
                               d_X + (((t + 1) * 8 + bt) * EMB) * 8 + tid * 4);
                cp_commit();
            }
            // ---- x-part GEMM (latency filler before the flag wait) ----
            const unsigned xb = xs0 + ((t & 1) ? 4096 : 0) + kc * 512;
#pragma unroll
            for (int q = 0; q < 4; ++q) {
                float4 w4 = wih[q];
#pragma unroll
                for (int cc = 0; cc < 4; ++cc) {
                    float wv = (cc == 0) ? w4.x : (cc == 1) ? w4.y : (cc == 2) ? w4.z : w4.w;
                    u64 wd = pack2(wv, wv);
                    u64 p0, p1, p2, p3;
                    unsigned ad = xb + (q * 4 + cc) * 32;
                    lds_2x64(p0, p1, ad);
                    lds_2x64(p2, p3, ad + 16);
                    ffma2(a0, wd, p0); ffma2(a1, wd, p1);
                    ffma2(a2, wd, p2); ffma2(a3, wd, p3);
                }
            }
        }

        if (t > 0) {
            // ---- fine-grained exchange: warp w waits on producer w, then
            //      streams its 512B h-block. Early blocks load while waiting
            //      for the slowest producer. ----
            const unsigned* fp = &d_flag[((t - 1) * 8 + bt) * 16 + w];
            while (ld_acq(fp) == 0) { }
            const float* src = d_H + (((t - 1) & 1) * 8 + bt) * (HID * 8)
                               + w * 128 + lane * 4;
            cp_async16(hsb + w * 512 + lane * 16, src);
            cp_commit();
            cp_wait0();
            __syncthreads();                        // whole h(t-1) tile visible

            // ---- h-part GEMM ----
#pragma unroll
            for (int q = 0; q < 8; ++q) {
                float4 w4 = whh[q];
#pragma unroll
                for (int cc = 0; cc < 4; ++cc) {
                    float wv = (cc == 0) ? w4.x : (cc == 1) ? w4.y : (cc == 2) ? w4.z : w4.w;
                    u64 wd = pack2(wv, wv);
                    u64 p0, p1, p2, p3;
                    unsigned ad = hbase + (q * 4 + cc) * 32;
                    lds_2x64(p0, p1, ad);
                    lds_2x64(p2, p3, ad + 16);
                    ffma2(a0, wd, p0); ffma2(a1, wd, p1);
                    ffma2(a2, wd, p2); ffma2(a3, wd, p3);
                }
            }
        }

        sts_2x64(pbase, a0, a1);
        sts_2x64(pbase + 16, a2, a3);
        __syncthreads();

        // ---- reduce + gates + state update + h-block store ----
        if (tid < 128) {
            const int j2 = tid >> 3, b = tid & 7;
            float v[4];
#pragma unroll
            for (int g = 0; g < 4; ++g) {
                int rr = g * 16 + j2;
                float s = bsh[rr];
#pragma unroll
                for (int k8 = 0; k8 < 8; ++k8) s += psh[k8 * 512 + rr * 8 + b];
                v[g] = s;
            }
            float ig = sigf(v[0]);
            float fg = sigf(v[1]);
            float gv = tanh_f(v[2]);
            float og = sigf(v[3]);
            c = fg * c + ig * gv;
            float h = og * tanh_f(c);
            __stcg(&d_H[((t & 1) * 8 + bt) * (HID * 8) + (ht * 16 + j2) * 8 + b], h);
        }
        __syncthreads();   // all h stores ordered before tid0's release

        if (tid == 0 && t < T_STEPS - 1)
            st_rel(&d_flag[(t * 8 + bt) * 16 + ht], 1u);
        // psh/hsh WAR for next iter protected by the syncthreads above + [B] sync
    }
}

// ============================================================================
// Kernel 3: logits = h @ lin_W.T + lin_b  ([64,256] x [256,32000]), f32x2
// ============================================================================
__global__ void __launch_bounds__(256, 1)
out_kernel(const float* __restrict__ lin_W, const float* __restrict__ lin_b,
           float* __restrict__ out) {
    extern __shared__ float hsh[];  // [256 k][64 b], 64 KB
    const int tid = threadIdx.x;
    {
        // d_H buf0 [bt8][k256][8b] -> hsh [k][64b]
        const float4* src = (const float4*)d_H;
        for (int idx4 = tid; idx4 < 4096; idx4 += 256) {
            int btx = idx4 >> 9, k = (idx4 >> 1) & 255, half = idx4 & 1;
            float4 v = src[idx4];
            *(float4*)(hsh + k * 64 + btx * 8 + half * 4) = v;
        }
    }
    __syncthreads();

    const int v = blockIdx.x * 256 + tid;
    const unsigned hb = (unsigned)__cvta_generic_to_shared(hsh);

    float bbv = lin_b[v];
    u64 acc[32];
    u64 bp = pack2(bbv, bbv);
#pragma unroll
    for (int j = 0; j < 32; ++j) acc[j] = bp;

    const float4* wp = (const float4*)(lin_W + v * HID);
#pragma unroll 4
    for (int kk = 0; kk < HID / 4; ++kk) {
        float4 w4 = wp[kk];
#pragma unroll
        for (int cc = 0; cc < 4; ++cc) {
            float w = (cc == 0) ? w4.x : (cc == 1) ? w4.y : (cc == 2) ? w4.z : w4.w;
            u64 wd = pack2(w, w);
            unsigned base = hb + ((kk * 4 + cc) * BSZ) * 4;
#pragma unroll
            for (int p = 0; p < 8; ++p) {
                u64 q0, q1, q2, q3;
                lds_2x64(q0, q1, base + p * 32);
                lds_2x64(q2, q3, base + p * 32 + 16);
                ffma2(acc[p * 4 + 0], wd, q0);
                ffma2(acc[p * 4 + 1], wd, q1);
                ffma2(acc[p * 4 + 2], wd, q2);
                ffma2(acc[p * 4 + 3], wd, q3);
            }
        }
    }
#pragma unroll
    for (int j = 0; j < 32; ++j) {
        float f0, f1;
        unpack2(acc[j], f0, f1);
        out[(2 * j) * VOCAB + v]     = f0;
        out[(2 * j + 1) * VOCAB + v] = f1;
    }
}

// ============================================================================
// launch
// ============================================================================
extern "C" void kernel_launch(void* const* d_in, const int* in_sizes, int n_in,
                              void* d_out, int out_size) {
    const int*   story  = (const int*)d_in[0];
    const int*   query  = (const int*)d_in[1];
    const float* E      = (const float*)d_in[2];
    const float* W_ih   = (const float*)d_in[3];
    const float* W_hh   = (const float*)d_in[4];
    const float* b_ih   = (const float*)d_in[5];
    const float* b_hh   = (const float*)d_in[6];
    const float* lin_W  = (const float*)d_in[7];
    const float* lin_b  = (const float*)d_in[8];
    float*       out    = (float*)d_out;

    cudaFuncSetAttribute(out_kernel, cudaFuncAttributeMaxDynamicSharedMemorySize,
                         HID * BSZ * 4);

    clear_flags_kernel<<<(NFLAGS + 255) / 256, 256>>>();
    encode_kernel<<<(T_STEPS * BSZ) / 8, 256>>>(story, query, E);
    lstm_kernel<<<RGRID, RTHREADS>>>(W_ih, W_hh, b_ih, b_hh);
    out_kernel<<<VOCAB / 256, 256, HID * BSZ * 4>>>(lin_W, lin_b, out);
}